// round 1
// baseline (speedup 1.0000x reference)
#include <cuda_runtime.h>
#include <math.h>

#define BATCH   2
#define S_LEN   2048
#define EMB     1024
#define HEADS   16
#define HD      64
#define NEG_VAL 100000.0f

// Scratch: device globals (no runtime allocation allowed).
__device__ float g_qkv[(size_t)BATCH * S_LEN * 3 * EMB];   // [B, S, 3E]
__device__ float g_att[(size_t)BATCH * S_LEN * EMB];       // [B, S, E]

// ---------------------------------------------------------------------------
// Tiled SGEMM with bias: C[M,N] = A[M,K] @ B[K,N] + bias[N]
// BM=BN=128, BK=8, 256 threads, 8x8 per-thread microtile.
// M,N,K all multiples of 128/8 for this problem -> no bounds checks.
// ---------------------------------------------------------------------------
__global__ __launch_bounds__(256) void sgemm_bias(
    const float* __restrict__ A, const float* __restrict__ B,
    const float* __restrict__ bias, float* __restrict__ C,
    int M, int N, int K)
{
    __shared__ float As[8][128];   // transposed A tile: As[k][m]
    __shared__ float Bs[8][128];   // Bs[k][n]

    const int tid = threadIdx.x;
    const int bx = blockIdx.x;     // N tile
    const int by = blockIdx.y;     // M tile

    const int arow = tid >> 1;          // 0..127
    const int acol = (tid & 1) * 4;     // 0 or 4
    const int brow = tid >> 5;          // 0..7
    const int bcol = (tid & 31) * 4;    // 0..124

    const float* Ag = A + (size_t)(by * 128 + arow) * K + acol;
    const float* Bg = B + (size_t)brow * N + bx * 128 + bcol;

    const int tx = tid & 15;   // 0..15 -> col group
    const int ty = tid >> 4;   // 0..15 -> row group

    float acc[8][8];
#pragma unroll
    for (int i = 0; i < 8; i++)
#pragma unroll
        for (int j = 0; j < 8; j++) acc[i][j] = 0.0f;

    for (int k0 = 0; k0 < K; k0 += 8) {
        float4 av = *(const float4*)Ag; Ag += 8;
        float4 bv = *(const float4*)Bg; Bg += (size_t)8 * N;

        As[acol + 0][arow] = av.x;
        As[acol + 1][arow] = av.y;
        As[acol + 2][arow] = av.z;
        As[acol + 3][arow] = av.w;
        *(float4*)&Bs[brow][bcol] = bv;
        __syncthreads();

#pragma unroll
        for (int kk = 0; kk < 8; kk++) {
            float a[8], b[8];
#pragma unroll
            for (int i = 0; i < 8; i++) a[i] = As[kk][ty * 8 + i];
#pragma unroll
            for (int j = 0; j < 8; j++) b[j] = Bs[kk][tx * 8 + j];
#pragma unroll
            for (int i = 0; i < 8; i++)
#pragma unroll
                for (int j = 0; j < 8; j++)
                    acc[i][j] += a[i] * b[j];
        }
        __syncthreads();
    }

    float bb[8];
#pragma unroll
    for (int j = 0; j < 8; j++) bb[j] = bias[bx * 128 + tx * 8 + j];

    float* Cg = C + (size_t)(by * 128 + ty * 8) * N + bx * 128 + tx * 8;
#pragma unroll
    for (int i = 0; i < 8; i++) {
        float4 o0, o1;
        o0.x = acc[i][0] + bb[0]; o0.y = acc[i][1] + bb[1];
        o0.z = acc[i][2] + bb[2]; o0.w = acc[i][3] + bb[3];
        o1.x = acc[i][4] + bb[4]; o1.y = acc[i][5] + bb[5];
        o1.z = acc[i][6] + bb[6]; o1.w = acc[i][7] + bb[7];
        *(float4*)(Cg + (size_t)i * N)     = o0;
        *(float4*)(Cg + (size_t)i * N + 4) = o1;
    }
}

// ---------------------------------------------------------------------------
// Flash-style causal attention, fp32.
// One block per (b, h, 64-row Q tile). 256 threads (16x16), 4x4 microtiles.
// Q/K stored d-major (transposed) in smem; scores staged through smem for the
// online-softmax pass.
// qkv layout: q(b,h,s,i) = g_qkv[(b*S+s)*3E + h*3d + i], k at +d, v at +2d.
// Output: g_att[b, s, h*d + c]   (heads merged back, ready for proj GEMM)
// ---------------------------------------------------------------------------
#define TPAD 65

__global__ __launch_bounds__(256) void attn_kernel()
{
    extern __shared__ float sm[];
    float* Qt  = sm;                 // [64][TPAD], d-major: Qt[d][r]
    float* Kt  = Qt + 64 * TPAD;     // [64][TPAD], d-major: Kt[d][c]
    float* Vs  = Kt + 64 * TPAD;     // [64][TPAD], natural: Vs[k][c]
    float* Ss  = Vs + 64 * TPAD;     // [64][TPAD], scores / probs
    float* m_s = Ss + 64 * TPAD;     // [64] running max
    float* l_s = m_s + 64;           // [64] running sum
    float* f_s = l_s + 64;           // [64] rescale factor

    const int tid = threadIdx.x;
    const int qt = blockIdx.x;       // 0..31
    const int h  = blockIdx.y;
    const int b  = blockIdx.z;
    const int qbase = qt * 64;

    const int tx = tid & 15;
    const int ty = tid >> 4;

    const size_t rowstride = 3 * EMB;
    const size_t hoff = ((size_t)b * S_LEN) * rowstride + (size_t)h * (3 * HD);

    // Load Q tile transposed (d-major).
    for (int e = tid; e < 64 * 64; e += 256) {
        int r = e >> 6, c = e & 63;
        Qt[c * TPAD + r] = g_qkv[hoff + (size_t)(qbase + r) * rowstride + c];
    }
    if (tid < 64) { m_s[tid] = -INFINITY; l_s[tid] = 0.0f; }

    float o[4][4];
#pragma unroll
    for (int i = 0; i < 4; i++)
#pragma unroll
        for (int j = 0; j < 4; j++) o[i][j] = 0.0f;

    __syncthreads();

    for (int jt = 0; jt <= qt; jt++) {
        const int kbase = jt * 64;

        // Load K (transposed) and V (natural) tiles.
        for (int e = tid; e < 64 * 64; e += 256) {
            int r = e >> 6, c = e & 63;
            size_t g = hoff + (size_t)(kbase + r) * rowstride + c;
            Kt[c * TPAD + r] = g_qkv[g + HD];
            Vs[r * TPAD + c] = g_qkv[g + 2 * HD];
        }
        __syncthreads();

        // Scores: S = Q @ K^T / sqrt(d)
        float sacc[4][4];
#pragma unroll
        for (int i = 0; i < 4; i++)
#pragma unroll
            for (int j = 0; j < 4; j++) sacc[i][j] = 0.0f;

        for (int d = 0; d < 64; d++) {
            float qa[4], kb[4];
#pragma unroll
            for (int i = 0; i < 4; i++) qa[i] = Qt[d * TPAD + ty * 4 + i];
#pragma unroll
            for (int j = 0; j < 4; j++) kb[j] = Kt[d * TPAD + tx * 4 + j];
#pragma unroll
            for (int i = 0; i < 4; i++)
#pragma unroll
                for (int j = 0; j < 4; j++)
                    sacc[i][j] += qa[i] * kb[j];
        }

        const bool diag = (jt == qt);
#pragma unroll
        for (int i = 0; i < 4; i++) {
#pragma unroll
            for (int j = 0; j < 4; j++) {
                float v = sacc[i][j] * 0.125f;   // 1/sqrt(64)
                if (diag && (kbase + tx * 4 + j > qbase + ty * 4 + i))
                    v = -NEG_VAL;                // exact mask math of reference
                Ss[(ty * 4 + i) * TPAD + tx * 4 + j] = v;
            }
        }
        __syncthreads();

        // Online softmax update (one thread per query row).
        if (tid < 64) {
            const int r = tid;
            float mo = m_s[r];
            float tm = -INFINITY;
#pragma unroll 8
            for (int c = 0; c < 64; c++) tm = fmaxf(tm, Ss[r * TPAD + c]);
            float mn = fmaxf(mo, tm);
            float fc = __expf(mo - mn);
            float sum = 0.0f;
#pragma unroll 8
            for (int c = 0; c < 64; c++) {
                float p = __expf(Ss[r * TPAD + c] - mn);
                Ss[r * TPAD + c] = p;
                sum += p;
            }
            l_s[r] = l_s[r] * fc + sum;
            m_s[r] = mn;
            f_s[r] = fc;
        }
        __syncthreads();

        // Rescale accumulators and O += P @ V
        float fr[4];
#pragma unroll
        for (int i = 0; i < 4; i++) fr[i] = f_s[ty * 4 + i];
#pragma unroll
        for (int i = 0; i < 4; i++)
#pragma unroll
            for (int j = 0; j < 4; j++) o[i][j] *= fr[i];

        for (int kk = 0; kk < 64; kk++) {
            float p[4], v[4];
#pragma unroll
            for (int i = 0; i < 4; i++) p[i] = Ss[(ty * 4 + i) * TPAD + kk];
#pragma unroll
            for (int j = 0; j < 4; j++) v[j] = Vs[kk * TPAD + tx * 4 + j];
#pragma unroll
            for (int i = 0; i < 4; i++)
#pragma unroll
                for (int j = 0; j < 4; j++)
                    o[i][j] += p[i] * v[j];
        }
        __syncthreads();   // protect smem tiles before next iteration's loads
    }

    // Normalize and write to merged-head layout.
    float inv[4];
#pragma unroll
    for (int i = 0; i < 4; i++) inv[i] = 1.0f / l_s[ty * 4 + i];

#pragma unroll
    for (int i = 0; i < 4; i++) {
#pragma unroll
        for (int j = 0; j < 4; j++) {
            size_t row = (size_t)b * S_LEN + qbase + ty * 4 + i;
            g_att[row * EMB + h * HD + tx * 4 + j] = o[i][j] * inv[i];
        }
    }
}

// ---------------------------------------------------------------------------
// Launch
// ---------------------------------------------------------------------------
extern "C" void kernel_launch(void* const* d_in, const int* in_sizes, int n_in,
                              void* d_out, int out_size)
{
    const float* x      = (const float*)d_in[0];
    const float* w_attn = (const float*)d_in[1];
    const float* b_attn = (const float*)d_in[2];
    const float* w_proj = (const float*)d_in[3];
    const float* b_proj = (const float*)d_in[4];
    float* out = (float*)d_out;

    float* qkv; float* att;
    cudaGetSymbolAddress((void**)&qkv, g_qkv);
    cudaGetSymbolAddress((void**)&att, g_att);

    const int M = BATCH * S_LEN;   // 4096

    // 1) QKV projection: [4096,1024] @ [1024,3072] + bias
    {
        dim3 grid((3 * EMB) / 128, M / 128);
        sgemm_bias<<<grid, 256>>>(x, w_attn, b_attn, qkv, M, 3 * EMB, EMB);
    }

    // 2) Causal multi-head attention
    {
        int smem = (4 * 64 * TPAD + 3 * 64) * (int)sizeof(float);
        cudaFuncSetAttribute(attn_kernel,
                             cudaFuncAttributeMaxDynamicSharedMemorySize, smem);
        dim3 grid(S_LEN / 64, HEADS, BATCH);
        attn_kernel<<<grid, 256, smem>>>();
    }

    // 3) Output projection: [4096,1024] @ [1024,1024] + bias
    {
        dim3 grid(EMB / 128, M / 128);
        sgemm_bias<<<grid, 256>>>(att, w_proj, b_proj, out, M, EMB, EMB);
    }
}

// round 3
// speedup vs baseline: 1.3884x; 1.3884x over previous
#include <cuda_runtime.h>
#include <cuda_bf16.h>
#include <math.h>
#include <stdint.h>

#define BATCH   2
#define S_LEN   2048
#define EMB     1024
#define HEADS   16
#define HD      64
#define NEG_VAL 100000.0f
#define MTOT    (BATCH * S_LEN)      // 4096

// ---------------------------------------------------------------------------
// Scratch (device globals; no runtime allocation allowed).
// ---------------------------------------------------------------------------
__device__ float          g_qkv[(size_t)MTOT * 3 * EMB];        // [M, 3E] fp32
__device__ unsigned short g_xhi[(size_t)MTOT * EMB];            // x split bf16 [M][K]
__device__ unsigned short g_xlo[(size_t)MTOT * EMB];
__device__ unsigned short g_wah[(size_t)(3 * EMB) * EMB];       // w_attn^T split [N][K]
__device__ unsigned short g_wal[(size_t)(3 * EMB) * EMB];
__device__ unsigned short g_wph[(size_t)EMB * EMB];             // w_proj^T split [N][K]
__device__ unsigned short g_wpl[(size_t)EMB * EMB];
__device__ unsigned short g_athi[(size_t)MTOT * EMB];           // attn out split [M][K]
__device__ unsigned short g_atlo[(size_t)MTOT * EMB];

// ---------------------------------------------------------------------------
// Helpers
// ---------------------------------------------------------------------------
__device__ __forceinline__ uint32_t smem_to_u32(const void* p) {
    uint32_t a;
    asm("{ .reg .u64 t; cvta.to.shared.u64 t, %1; cvt.u32.u64 %0, t; }" : "=r"(a) : "l"(p));
    return a;
}

#define CP_ASYNC16(dst, src) \
    asm volatile("cp.async.cg.shared.global [%0], [%1], 16;" :: "r"(dst), "l"(src))
#define CP_COMMIT() asm volatile("cp.async.commit_group;")
#define CP_WAIT1()  asm volatile("cp.async.wait_group 1;")
#define CP_WAIT0()  asm volatile("cp.async.wait_group 0;")

#define LDMX4(r0, r1, r2, r3, addr) \
    asm volatile("ldmatrix.sync.aligned.m8n8.x4.shared.b16 {%0,%1,%2,%3}, [%4];" \
                 : "=r"(r0), "=r"(r1), "=r"(r2), "=r"(r3) : "r"(addr))

__device__ __forceinline__ void mma_bf16(float* d, const uint32_t* a, const uint32_t* b)
{
    asm volatile(
        "mma.sync.aligned.m16n8k16.row.col.f32.bf16.bf16.f32 "
        "{%0,%1,%2,%3}, {%4,%5,%6,%7}, {%8,%9}, {%0,%1,%2,%3};"
        : "+f"(d[0]), "+f"(d[1]), "+f"(d[2]), "+f"(d[3])
        : "r"(a[0]), "r"(a[1]), "r"(a[2]), "r"(a[3]), "r"(b[0]), "r"(b[1]));
}

// ---------------------------------------------------------------------------
// Conversion kernels: fp32 -> bf16 hi/lo split
// ---------------------------------------------------------------------------
__global__ void convert_split(const float* __restrict__ in,
                              unsigned short* __restrict__ hi,
                              unsigned short* __restrict__ lo, int n)
{
    int i = blockIdx.x * blockDim.x + threadIdx.x;
    if (i < n) {
        float v = in[i];
        __nv_bfloat16 h = __float2bfloat16(v);
        __nv_bfloat16 l = __float2bfloat16(v - __bfloat162float(h));
        hi[i] = *(unsigned short*)&h;
        lo[i] = *(unsigned short*)&l;
    }
}

// W[K][N] fp32 row-major  ->  hi/lo [N][K] bf16 (transposed, K-major)
__global__ void convert_transpose(const float* __restrict__ W,
                                  unsigned short* __restrict__ hi,
                                  unsigned short* __restrict__ lo, int K, int N)
{
    __shared__ float t[32][33];
    int n0 = blockIdx.x * 32, k0 = blockIdx.y * 32;
    int tx = threadIdx.x, ty = threadIdx.y;     // 32 x 8
#pragma unroll
    for (int i = 0; i < 4; i++)
        t[ty + i * 8][tx] = W[(size_t)(k0 + ty + i * 8) * N + n0 + tx];
    __syncthreads();
#pragma unroll
    for (int i = 0; i < 4; i++) {
        float v = t[tx][ty + i * 8];
        __nv_bfloat16 h = __float2bfloat16(v);
        __nv_bfloat16 l = __float2bfloat16(v - __bfloat162float(h));
        size_t o = (size_t)(n0 + ty + i * 8) * K + k0 + tx;
        hi[o] = *(unsigned short*)&h;
        lo[o] = *(unsigned short*)&l;
    }
}

// ---------------------------------------------------------------------------
// mma.sync split-bf16 GEMM:  C[M,N] = A[M,K] @ B^T[N,K] + bias[N]   (fp32 out)
// 128x128 CTA tile, BK=32, 256 threads (8 warps of 64x32), cp.async 2-stage.
// Smem rows padded to 80B -> every ldmatrix phase is bank-conflict-free.
// ---------------------------------------------------------------------------
#define TROW      80                           // bytes per smem row (64 data + 16 pad)
#define TILE_B    (128 * TROW)                 // 10240
#define STAGE_B   (4 * TILE_B)                 // Ahi, Alo, Bhi, Blo
#define GEMM_SMEM (2 * STAGE_B)                // 81920

__global__ __launch_bounds__(256) void gemm_mma_split(
    const unsigned short* __restrict__ Ahi, const unsigned short* __restrict__ Alo,
    const unsigned short* __restrict__ Bhi, const unsigned short* __restrict__ Blo,
    const float* __restrict__ bias, float* __restrict__ C,
    int M, int N, int K)
{
    extern __shared__ char smem[];
    const uint32_t sb0 = smem_to_u32(smem);
    const int tid = threadIdx.x;
    const int wid = tid >> 5;
    const int l   = tid & 31;
    const int bx = blockIdx.x;    // N tile
    const int by = blockIdx.y;    // M tile

    const int wm = wid >> 2;      // 0..1  (m offset wm*64)
    const int wn = wid & 3;       // 0..3  (n offset wn*32)

    // cp.async slots: per tile, 512 chunks of 16B; this thread does chunks tid, tid+256.
    // chunk c -> row = c>>2, colchunk = c&3.
    int r0 = tid >> 2,        cc0 = tid & 3;
    int r1 = (tid + 256) >> 2, cc1 = tid & 3;   // (tid+256)&3 == tid&3
    uint32_t so0 = (uint32_t)r0 * TROW + cc0 * 16;
    uint32_t so1 = (uint32_t)r1 * TROW + cc1 * 16;
    size_t ga0 = (size_t)(by * 128 + r0) * K + cc0 * 8;
    size_t ga1 = (size_t)(by * 128 + r1) * K + cc1 * 8;
    size_t gb0 = (size_t)(bx * 128 + r0) * K + cc0 * 8;
    size_t gb1 = (size_t)(bx * 128 + r1) * K + cc1 * 8;

    const int NT = K / 32;

    // issue stage kt into buffer kt&1
    auto issue = [&](int kt) {
        uint32_t sb = sb0 + (uint32_t)(kt & 1) * STAGE_B;
        size_t ko = (size_t)kt * 32;
        CP_ASYNC16(sb + 0 * TILE_B + so0, Ahi + ga0 + ko);
        CP_ASYNC16(sb + 0 * TILE_B + so1, Ahi + ga1 + ko);
        CP_ASYNC16(sb + 1 * TILE_B + so0, Alo + ga0 + ko);
        CP_ASYNC16(sb + 1 * TILE_B + so1, Alo + ga1 + ko);
        CP_ASYNC16(sb + 2 * TILE_B + so0, Bhi + gb0 + ko);
        CP_ASYNC16(sb + 2 * TILE_B + so1, Bhi + gb1 + ko);
        CP_ASYNC16(sb + 3 * TILE_B + so0, Blo + gb0 + ko);
        CP_ASYNC16(sb + 3 * TILE_B + so1, Blo + gb1 + ko);
        CP_COMMIT();
    };

    float acc[4][4][4];
#pragma unroll
    for (int mi = 0; mi < 4; mi++)
#pragma unroll
        for (int j = 0; j < 4; j++)
#pragma unroll
            for (int e = 0; e < 4; e++) acc[mi][j][e] = 0.0f;

    // ldmatrix per-lane offsets (within a tile)
    const uint32_t a_lane = (uint32_t)(wm * 64 + (l & 15)) * TROW + (l >> 4) * 16;
    const uint32_t b_lane = (uint32_t)(wn * 32 + (l & 7) + ((l >> 4) * 8)) * TROW
                          + ((l >> 3) & 1) * 16;

    issue(0);

    for (int kt = 0; kt < NT; kt++) {
        if (kt + 1 < NT) { issue(kt + 1); CP_WAIT1(); }
        else             { CP_WAIT0(); }
        __syncthreads();

        uint32_t sb = sb0 + (uint32_t)(kt & 1) * STAGE_B;

#pragma unroll
        for (int ks8 = 0; ks8 < 2; ks8++) {
            const uint32_t ko = ks8 * 32;          // 16 elems * 2B
            uint32_t ah[4][4], al[4][4], bh[2][4], bl[2][4];
#pragma unroll
            for (int mi = 0; mi < 4; mi++) {
                uint32_t ad = sb + a_lane + mi * (16 * TROW) + ko;
                LDMX4(ah[mi][0], ah[mi][1], ah[mi][2], ah[mi][3], ad);
                LDMX4(al[mi][0], al[mi][1], al[mi][2], al[mi][3], ad + TILE_B);
            }
#pragma unroll
            for (int nb = 0; nb < 2; nb++) {
                uint32_t bd = sb + 2 * TILE_B + b_lane + nb * (16 * TROW) + ko;
                LDMX4(bh[nb][0], bh[nb][1], bh[nb][2], bh[nb][3], bd);
                LDMX4(bl[nb][0], bl[nb][1], bl[nb][2], bl[nb][3], bd + TILE_B);
            }
            // pass 0: Ah*Bh, pass 1: Ah*Bl, pass 2: Al*Bh
#pragma unroll
            for (int mi = 0; mi < 4; mi++)
#pragma unroll
                for (int j = 0; j < 4; j++)
                    mma_bf16(acc[mi][j], ah[mi], &bh[j >> 1][(j & 1) * 2]);
#pragma unroll
            for (int mi = 0; mi < 4; mi++)
#pragma unroll
                for (int j = 0; j < 4; j++)
                    mma_bf16(acc[mi][j], ah[mi], &bl[j >> 1][(j & 1) * 2]);
#pragma unroll
            for (int mi = 0; mi < 4; mi++)
#pragma unroll
                for (int j = 0; j < 4; j++)
                    mma_bf16(acc[mi][j], al[mi], &bh[j >> 1][(j & 1) * 2]);
        }
        __syncthreads();
    }

    // Epilogue: direct global stores with bias.
#pragma unroll
    for (int mi = 0; mi < 4; mi++) {
        int row = by * 128 + wm * 64 + mi * 16 + (l >> 2);
#pragma unroll
        for (int j = 0; j < 4; j++) {
            int col = bx * 128 + wn * 32 + j * 8 + (l & 3) * 2;
            float b0 = bias[col], b1 = bias[col + 1];
            float2 v0 = make_float2(acc[mi][j][0] + b0, acc[mi][j][1] + b1);
            float2 v1 = make_float2(acc[mi][j][2] + b0, acc[mi][j][3] + b1);
            *(float2*)(C + (size_t)row * N + col)       = v0;
            *(float2*)(C + (size_t)(row + 8) * N + col) = v1;
        }
    }
}

// ---------------------------------------------------------------------------
// Flash-style causal attention, fp32; writes bf16 hi/lo out.
// ---------------------------------------------------------------------------
#define TPAD 65

__global__ __launch_bounds__(256) void attn_kernel()
{
    extern __shared__ float sm[];
    float* Qt  = sm;
    float* Kt  = Qt + 64 * TPAD;
    float* Vs  = Kt + 64 * TPAD;
    float* Ss  = Vs + 64 * TPAD;
    float* m_s = Ss + 64 * TPAD;
    float* l_s = m_s + 64;
    float* f_s = l_s + 64;

    const int tid = threadIdx.x;
    const int qt = blockIdx.x;
    const int h  = blockIdx.y;
    const int b  = blockIdx.z;
    const int qbase = qt * 64;

    const int tx = tid & 15;
    const int ty = tid >> 4;

    const size_t rowstride = 3 * EMB;
    const size_t hoff = ((size_t)b * S_LEN) * rowstride + (size_t)h * (3 * HD);

    for (int e = tid; e < 64 * 64; e += 256) {
        int r = e >> 6, c = e & 63;
        Qt[c * TPAD + r] = g_qkv[hoff + (size_t)(qbase + r) * rowstride + c];
    }
    if (tid < 64) { m_s[tid] = -INFINITY; l_s[tid] = 0.0f; }

    float o[4][4];
#pragma unroll
    for (int i = 0; i < 4; i++)
#pragma unroll
        for (int j = 0; j < 4; j++) o[i][j] = 0.0f;

    __syncthreads();

    for (int jt = 0; jt <= qt; jt++) {
        const int kbase = jt * 64;
        for (int e = tid; e < 64 * 64; e += 256) {
            int r = e >> 6, c = e & 63;
            size_t g = hoff + (size_t)(kbase + r) * rowstride + c;
            Kt[c * TPAD + r] = g_qkv[g + HD];
            Vs[r * TPAD + c] = g_qkv[g + 2 * HD];
        }
        __syncthreads();

        float sacc[4][4];
#pragma unroll
        for (int i = 0; i < 4; i++)
#pragma unroll
            for (int j = 0; j < 4; j++) sacc[i][j] = 0.0f;

        for (int d = 0; d < 64; d++) {
            float qa[4], kb[4];
#pragma unroll
            for (int i = 0; i < 4; i++) qa[i] = Qt[d * TPAD + ty * 4 + i];
#pragma unroll
            for (int j = 0; j < 4; j++) kb[j] = Kt[d * TPAD + tx * 4 + j];
#pragma unroll
            for (int i = 0; i < 4; i++)
#pragma unroll
                for (int j = 0; j < 4; j++)
                    sacc[i][j] += qa[i] * kb[j];
        }

        const bool diag = (jt == qt);
#pragma unroll
        for (int i = 0; i < 4; i++) {
#pragma unroll
            for (int j = 0; j < 4; j++) {
                float v = sacc[i][j] * 0.125f;
                if (diag && (kbase + tx * 4 + j > qbase + ty * 4 + i))
                    v = -NEG_VAL;
                Ss[(ty * 4 + i) * TPAD + tx * 4 + j] = v;
            }
        }
        __syncthreads();

        if (tid < 64) {
            const int r = tid;
            float mo = m_s[r];
            float tm = -INFINITY;
#pragma unroll 8
            for (int c = 0; c < 64; c++) tm = fmaxf(tm, Ss[r * TPAD + c]);
            float mn = fmaxf(mo, tm);
            float fc = __expf(mo - mn);
            float sum = 0.0f;
#pragma unroll 8
            for (int c = 0; c < 64; c++) {
                float p = __expf(Ss[r * TPAD + c] - mn);
                Ss[r * TPAD + c] = p;
                sum += p;
            }
            l_s[r] = l_s[r] * fc + sum;
            m_s[r] = mn;
            f_s[r] = fc;
        }
        __syncthreads();

        float fr[4];
#pragma unroll
        for (int i = 0; i < 4; i++) fr[i] = f_s[ty * 4 + i];
#pragma unroll
        for (int i = 0; i < 4; i++)
#pragma unroll
            for (int j = 0; j < 4; j++) o[i][j] *= fr[i];

        for (int kk = 0; kk < 64; kk++) {
            float p[4], v[4];
#pragma unroll
            for (int i = 0; i < 4; i++) p[i] = Ss[(ty * 4 + i) * TPAD + kk];
#pragma unroll
            for (int j = 0; j < 4; j++) v[j] = Vs[kk * TPAD + tx * 4 + j];
#pragma unroll
            for (int i = 0; i < 4; i++)
#pragma unroll
                for (int j = 0; j < 4; j++)
                    o[i][j] += p[i] * v[j];
        }
        __syncthreads();
    }

    float inv[4];
#pragma unroll
    for (int i = 0; i < 4; i++) inv[i] = 1.0f / l_s[ty * 4 + i];

#pragma unroll
    for (int i = 0; i < 4; i++) {
#pragma unroll
        for (int j = 0; j < 4; j++) {
            size_t row = (size_t)b * S_LEN + qbase + ty * 4 + i;
            float val = o[i][j] * inv[i];
            __nv_bfloat16 hh = __float2bfloat16(val);
            __nv_bfloat16 ll = __float2bfloat16(val - __bfloat162float(hh));
            size_t oidx = row * EMB + h * HD + tx * 4 + j;
            g_athi[oidx] = *(unsigned short*)&hh;
            g_atlo[oidx] = *(unsigned short*)&ll;
        }
    }
}

// ---------------------------------------------------------------------------
// Launch
// ---------------------------------------------------------------------------
extern "C" void kernel_launch(void* const* d_in, const int* in_sizes, int n_in,
                              void* d_out, int out_size)
{
    const float* x      = (const float*)d_in[0];
    const float* w_attn = (const float*)d_in[1];
    const float* b_attn = (const float*)d_in[2];
    const float* w_proj = (const float*)d_in[3];
    const float* b_proj = (const float*)d_in[4];
    float* out = (float*)d_out;

    float *qkv;
    unsigned short *xhi, *xlo, *wah, *wal, *wph, *wpl, *athi, *atlo;
    cudaGetSymbolAddress((void**)&qkv,  g_qkv);
    cudaGetSymbolAddress((void**)&xhi,  g_xhi);
    cudaGetSymbolAddress((void**)&xlo,  g_xlo);
    cudaGetSymbolAddress((void**)&wah,  g_wah);
    cudaGetSymbolAddress((void**)&wal,  g_wal);
    cudaGetSymbolAddress((void**)&wph,  g_wph);
    cudaGetSymbolAddress((void**)&wpl,  g_wpl);
    cudaGetSymbolAddress((void**)&athi, g_athi);
    cudaGetSymbolAddress((void**)&atlo, g_atlo);

    cudaFuncSetAttribute(gemm_mma_split,
                         cudaFuncAttributeMaxDynamicSharedMemorySize, GEMM_SMEM);
    int asmem = (4 * 64 * TPAD + 3 * 64) * (int)sizeof(float);
    cudaFuncSetAttribute(attn_kernel,
                         cudaFuncAttributeMaxDynamicSharedMemorySize, asmem);

    // 1) Split inputs / weights to bf16 hi+lo (weights transposed to [N][K])
    {
        int n = MTOT * EMB;
        convert_split<<<(n + 255) / 256, 256>>>(x, xhi, xlo, n);
        convert_transpose<<<dim3((3 * EMB) / 32, EMB / 32), dim3(32, 8)>>>(w_attn, wah, wal, EMB, 3 * EMB);
        convert_transpose<<<dim3(EMB / 32, EMB / 32), dim3(32, 8)>>>(w_proj, wph, wpl, EMB, EMB);
    }

    // 2) QKV projection: [4096,1024] @ [1024,3072] + bias
    {
        dim3 grid((3 * EMB) / 128, MTOT / 128);
        gemm_mma_split<<<grid, 256, GEMM_SMEM>>>(xhi, xlo, wah, wal, b_attn, qkv,
                                                 MTOT, 3 * EMB, EMB);
    }

    // 3) Causal multi-head attention (fp32), emits split-bf16 output
    {
        dim3 grid(S_LEN / 64, HEADS, BATCH);
        attn_kernel<<<grid, 256, asmem>>>();
    }

    // 4) Output projection: [4096,1024] @ [1024,1024] + bias
    {
        dim3 grid(EMB / 128, MTOT / 128);
        gemm_mma_split<<<grid, 256, GEMM_SMEM>>>(athi, atlo, wph, wpl, b_proj, out,
                                                 MTOT, EMB, EMB);
    }
}

// round 6
// speedup vs baseline: 2.7751x; 1.9987x over previous
#include <cuda_runtime.h>
#include <cuda_bf16.h>
#include <math.h>
#include <stdint.h>

#define BATCH   2
#define S_LEN   2048
#define EMB     1024
#define HEADS   16
#define HD      64
#define NEG_VAL 100000.0f
#define MTOT    (BATCH * S_LEN)      // 4096

typedef unsigned short ush;

// ---------------------------------------------------------------------------
// Scratch (device globals; no runtime allocation allowed).
// ---------------------------------------------------------------------------
__device__ __align__(256) float g_qkv[(size_t)MTOT * 3 * EMB];   // [M, 3E] fp32
__device__ __align__(256) ush g_xhi[(size_t)MTOT * EMB];
__device__ __align__(256) ush g_xlo[(size_t)MTOT * EMB];
__device__ __align__(256) ush g_wah[(size_t)(3 * EMB) * EMB];
__device__ __align__(256) ush g_wal[(size_t)(3 * EMB) * EMB];
__device__ __align__(256) ush g_wph[(size_t)EMB * EMB];
__device__ __align__(256) ush g_wpl[(size_t)EMB * EMB];
__device__ __align__(256) ush g_athi[(size_t)MTOT * EMB];
__device__ __align__(256) ush g_atlo[(size_t)MTOT * EMB];
// Per-head split Q/K/V: [b][h][s][d]
__device__ __align__(256) ush g_qh[(size_t)MTOT * EMB];
__device__ __align__(256) ush g_ql[(size_t)MTOT * EMB];
__device__ __align__(256) ush g_kh[(size_t)MTOT * EMB];
__device__ __align__(256) ush g_kl[(size_t)MTOT * EMB];
__device__ __align__(256) ush g_vh[(size_t)MTOT * EMB];
__device__ __align__(256) ush g_vl[(size_t)MTOT * EMB];

// ---------------------------------------------------------------------------
// Helpers
// ---------------------------------------------------------------------------
__device__ __forceinline__ uint32_t smem_to_u32(const void* p) {
    uint32_t a;
    asm("{ .reg .u64 t; cvta.to.shared.u64 t, %1; cvt.u32.u64 %0, t; }" : "=r"(a) : "l"(p));
    return a;
}

#define CP_ASYNC16(dst, src) \
    asm volatile("cp.async.cg.shared.global [%0], [%1], 16;" :: "r"(dst), "l"(src))
#define CP_COMMIT() asm volatile("cp.async.commit_group;")
#define CP_WAIT1()  asm volatile("cp.async.wait_group 1;")
#define CP_WAIT0()  asm volatile("cp.async.wait_group 0;")

#define LDMX4(r0, r1, r2, r3, addr) \
    asm volatile("ldmatrix.sync.aligned.m8n8.x4.shared.b16 {%0,%1,%2,%3}, [%4];" \
                 : "=r"(r0), "=r"(r1), "=r"(r2), "=r"(r3) : "r"(addr))
#define LDMX4T(r0, r1, r2, r3, addr) \
    asm volatile("ldmatrix.sync.aligned.m8n8.x4.trans.shared.b16 {%0,%1,%2,%3}, [%4];" \
                 : "=r"(r0), "=r"(r1), "=r"(r2), "=r"(r3) : "r"(addr))

__device__ __forceinline__ void mma_bf16(float* d, const uint32_t* a, const uint32_t* b)
{
    asm volatile(
        "mma.sync.aligned.m16n8k16.row.col.f32.bf16.bf16.f32 "
        "{%0,%1,%2,%3}, {%4,%5,%6,%7}, {%8,%9}, {%0,%1,%2,%3};"
        : "+f"(d[0]), "+f"(d[1]), "+f"(d[2]), "+f"(d[3])
        : "r"(a[0]), "r"(a[1]), "r"(a[2]), "r"(a[3]), "r"(b[0]), "r"(b[1]));
}

// hi split via mantissa truncation (exact residual), pack two hi-bf16
__device__ __forceinline__ uint32_t pack_hi(float e, float o) {
    uint32_t r;
    asm("prmt.b32 %0, %1, %2, 0x7632;" : "=r"(r)
        : "r"(__float_as_uint(e)), "r"(__float_as_uint(o)));
    return r;
}
__device__ __forceinline__ uint32_t pack_lo(float e, float o) {
    float le = e - __uint_as_float(__float_as_uint(e) & 0xFFFF0000u);
    float lo = o - __uint_as_float(__float_as_uint(o) & 0xFFFF0000u);
    uint32_t r;
    asm("cvt.rn.bf16x2.f32 %0, %1, %2;" : "=r"(r) : "f"(lo), "f"(le));
    return r;
}

// ---------------------------------------------------------------------------
// fp32 -> bf16 hi/lo split (GEMM operand prep)
// ---------------------------------------------------------------------------
__global__ void convert_split(const float* __restrict__ in,
                              ush* __restrict__ hi, ush* __restrict__ lo, int n)
{
    int i = blockIdx.x * blockDim.x + threadIdx.x;
    if (i < n) {
        float v = in[i];
        __nv_bfloat16 h = __float2bfloat16(v);
        __nv_bfloat16 l = __float2bfloat16(v - __bfloat162float(h));
        hi[i] = *(ush*)&h;
        lo[i] = *(ush*)&l;
    }
}

__global__ void convert_transpose(const float* __restrict__ W,
                                  ush* __restrict__ hi, ush* __restrict__ lo,
                                  int K, int N)
{
    __shared__ float t[32][33];
    int n0 = blockIdx.x * 32, k0 = blockIdx.y * 32;
    int tx = threadIdx.x, ty = threadIdx.y;
#pragma unroll
    for (int i = 0; i < 4; i++)
        t[ty + i * 8][tx] = W[(size_t)(k0 + ty + i * 8) * N + n0 + tx];
    __syncthreads();
#pragma unroll
    for (int i = 0; i < 4; i++) {
        float v = t[tx][ty + i * 8];
        __nv_bfloat16 h = __float2bfloat16(v);
        __nv_bfloat16 l = __float2bfloat16(v - __bfloat162float(h));
        size_t o = (size_t)(n0 + ty + i * 8) * K + k0 + tx;
        hi[o] = *(ush*)&h;
        lo[o] = *(ush*)&l;
    }
}

// qkv fp32 [b,s,3E] -> per-head split bf16 [b,h,s,d]; Q pre-scaled by 1/8 (exact)
__global__ void split_qkv(const float* __restrict__ qkv)
{
    int j = blockIdx.x * 256 + threadIdx.x;            // pair index, 2^21 total
    int dp = j & 31;
    int s  = (j >> 5) & 2047;
    int h  = (j >> 16) & 15;
    int b  = j >> 20;
    size_t src = ((size_t)(b * S_LEN + s)) * (3 * EMB) + h * 192 + dp * 2;
    size_t dst = (((size_t)(b * HEADS + h) * S_LEN + s) * HD >> 1) + dp; // u32 index

    float2 q = *(const float2*)(qkv + src);
    float2 k = *(const float2*)(qkv + src + 64);
    float2 v = *(const float2*)(qkv + src + 128);
    q.x *= 0.125f; q.y *= 0.125f;

    ((uint32_t*)g_qh)[dst] = pack_hi(q.x, q.y);
    ((uint32_t*)g_ql)[dst] = pack_lo(q.x, q.y);
    ((uint32_t*)g_kh)[dst] = pack_hi(k.x, k.y);
    ((uint32_t*)g_kl)[dst] = pack_lo(k.x, k.y);
    ((uint32_t*)g_vh)[dst] = pack_hi(v.x, v.y);
    ((uint32_t*)g_vl)[dst] = pack_lo(v.x, v.y);
}

// ---------------------------------------------------------------------------
// mma.sync split-bf16 GEMM (validated R3; rows = 32 elems = 64B + 16 pad)
// ---------------------------------------------------------------------------
#define TROW      80
#define TILE_B    (128 * TROW)
#define STAGE_B   (4 * TILE_B)
#define GEMM_SMEM (2 * STAGE_B)

__global__ __launch_bounds__(256) void gemm_mma_split(
    const ush* __restrict__ Ahi, const ush* __restrict__ Alo,
    const ush* __restrict__ Bhi, const ush* __restrict__ Blo,
    const float* __restrict__ bias, float* __restrict__ C,
    int M, int N, int K)
{
    extern __shared__ char smem[];
    const uint32_t sb0 = smem_to_u32(smem);
    const int tid = threadIdx.x;
    const int wid = tid >> 5;
    const int l   = tid & 31;
    const int bx = blockIdx.x;
    const int by = blockIdx.y;
    const int wm = wid >> 2;
    const int wn = wid & 3;

    int r0 = tid >> 2,         cc0 = tid & 3;
    int r1 = (tid + 256) >> 2, cc1 = tid & 3;
    uint32_t so0 = (uint32_t)r0 * TROW + cc0 * 16;
    uint32_t so1 = (uint32_t)r1 * TROW + cc1 * 16;
    size_t ga0 = (size_t)(by * 128 + r0) * K + cc0 * 8;
    size_t ga1 = (size_t)(by * 128 + r1) * K + cc1 * 8;
    size_t gb0 = (size_t)(bx * 128 + r0) * K + cc0 * 8;
    size_t gb1 = (size_t)(bx * 128 + r1) * K + cc1 * 8;

    const int NT = K / 32;

    auto issue = [&](int kt) {
        uint32_t sb = sb0 + (uint32_t)(kt & 1) * STAGE_B;
        size_t ko = (size_t)kt * 32;
        CP_ASYNC16(sb + 0 * TILE_B + so0, Ahi + ga0 + ko);
        CP_ASYNC16(sb + 0 * TILE_B + so1, Ahi + ga1 + ko);
        CP_ASYNC16(sb + 1 * TILE_B + so0, Alo + ga0 + ko);
        CP_ASYNC16(sb + 1 * TILE_B + so1, Alo + ga1 + ko);
        CP_ASYNC16(sb + 2 * TILE_B + so0, Bhi + gb0 + ko);
        CP_ASYNC16(sb + 2 * TILE_B + so1, Bhi + gb1 + ko);
        CP_ASYNC16(sb + 3 * TILE_B + so0, Blo + gb0 + ko);
        CP_ASYNC16(sb + 3 * TILE_B + so1, Blo + gb1 + ko);
        CP_COMMIT();
    };

    float acc[4][4][4];
#pragma unroll
    for (int mi = 0; mi < 4; mi++)
#pragma unroll
        for (int j = 0; j < 4; j++)
#pragma unroll
            for (int e = 0; e < 4; e++) acc[mi][j][e] = 0.0f;

    const uint32_t a_lane = (uint32_t)(wm * 64 + (l & 15)) * TROW + (l >> 4) * 16;
    const uint32_t b_lane = (uint32_t)(wn * 32 + (l & 7) + ((l >> 4) * 8)) * TROW
                          + ((l >> 3) & 1) * 16;

    issue(0);

    for (int kt = 0; kt < NT; kt++) {
        if (kt + 1 < NT) { issue(kt + 1); CP_WAIT1(); }
        else             { CP_WAIT0(); }
        __syncthreads();

        uint32_t sb = sb0 + (uint32_t)(kt & 1) * STAGE_B;

#pragma unroll
        for (int ks8 = 0; ks8 < 2; ks8++) {
            const uint32_t ko = ks8 * 32;
            uint32_t ah[4][4], al[4][4], bh[2][4], bl[2][4];
#pragma unroll
            for (int mi = 0; mi < 4; mi++) {
                uint32_t ad = sb + a_lane + mi * (16 * TROW) + ko;
                LDMX4(ah[mi][0], ah[mi][1], ah[mi][2], ah[mi][3], ad);
                LDMX4(al[mi][0], al[mi][1], al[mi][2], al[mi][3], ad + TILE_B);
            }
#pragma unroll
            for (int nb = 0; nb < 2; nb++) {
                uint32_t bd = sb + 2 * TILE_B + b_lane + nb * (16 * TROW) + ko;
                LDMX4(bh[nb][0], bh[nb][1], bh[nb][2], bh[nb][3], bd);
                LDMX4(bl[nb][0], bl[nb][1], bl[nb][2], bl[nb][3], bd + TILE_B);
            }
#pragma unroll
            for (int mi = 0; mi < 4; mi++)
#pragma unroll
                for (int j = 0; j < 4; j++)
                    mma_bf16(acc[mi][j], ah[mi], &bh[j >> 1][(j & 1) * 2]);
#pragma unroll
            for (int mi = 0; mi < 4; mi++)
#pragma unroll
                for (int j = 0; j < 4; j++)
                    mma_bf16(acc[mi][j], ah[mi], &bl[j >> 1][(j & 1) * 2]);
#pragma unroll
            for (int mi = 0; mi < 4; mi++)
#pragma unroll
                for (int j = 0; j < 4; j++)
                    mma_bf16(acc[mi][j], al[mi], &bh[j >> 1][(j & 1) * 2]);
        }
        __syncthreads();
    }

#pragma unroll
    for (int mi = 0; mi < 4; mi++) {
        int row = by * 128 + wm * 64 + mi * 16 + (l >> 2);
#pragma unroll
        for (int j = 0; j < 4; j++) {
            int col = bx * 128 + wn * 32 + j * 8 + (l & 3) * 2;
            float b0 = bias[col], b1 = bias[col + 1];
            float2 v0 = make_float2(acc[mi][j][0] + b0, acc[mi][j][1] + b1);
            float2 v1 = make_float2(acc[mi][j][2] + b0, acc[mi][j][3] + b1);
            *(float2*)(C + (size_t)row * N + col)       = v0;
            *(float2*)(C + (size_t)(row + 8) * N + col) = v1;
        }
    }
}

// ---------------------------------------------------------------------------
// Flash attention, split-bf16 mma.sync.
// Attention tiles are 128 rows x 64 bf16 = 128 B data/row; stride 144 B
// (36 words, 36 mod 32 = 4 -> all ldmatrix phases conflict-free).
// ---------------------------------------------------------------------------
#define AROW    144
#define ATILE   (128 * AROW)             // 18432
#define AQ_H    0
#define AQ_L    ATILE
#define ASTG    (2 * ATILE)              // stage base
#define ASTG_SZ (4 * ATILE)              // Kh,Kl,Vh,Vl per stage
#define ATT_SMEM (2 * ATILE + 2 * ASTG_SZ)   // 184320

__global__ __launch_bounds__(256) void attn_mma(
    const ush* __restrict__ Qh, const ush* __restrict__ Ql,
    const ush* __restrict__ Kh, const ush* __restrict__ Kl,
    const ush* __restrict__ Vh, const ush* __restrict__ Vl,
    ush* __restrict__ Ohi, ush* __restrict__ Olo)
{
    extern __shared__ char smem[];
    const uint32_t sb = smem_to_u32(smem);
    const int tid = threadIdx.x;
    const int w = tid >> 5;
    const int l = tid & 31;
    const int qt = (int)gridDim.x - 1 - (int)blockIdx.x;    // big tiles first
    const int h = blockIdx.y;
    const int b = blockIdx.z;
    const int qbase = qt * 128;

    const size_t headoff = (size_t)(b * HEADS + h) * S_LEN * HD;

    // 128x64 bf16 tile = 1024 16B-chunks; 4 per thread (8 chunks per row)
    auto issue_kv = [&](int kt) {
        uint32_t st = sb + ASTG + (uint32_t)(kt & 1) * ASTG_SZ;
        size_t gb = headoff + (size_t)kt * 128 * HD;
#pragma unroll
        for (int j = 0; j < 4; j++) {
            int c = tid + j * 256;
            int r = c >> 3;
            uint32_t dso = (uint32_t)r * AROW + (c & 7) * 16;
            size_t gso = gb + (size_t)r * HD + (c & 7) * 8;
            CP_ASYNC16(st + 0 * ATILE + dso, Kh + gso);
            CP_ASYNC16(st + 1 * ATILE + dso, Kl + gso);
            CP_ASYNC16(st + 2 * ATILE + dso, Vh + gso);
            CP_ASYNC16(st + 3 * ATILE + dso, Vl + gso);
        }
        CP_COMMIT();
    };

    // prologue group 0: Q tiles + KV stage 0
    {
        size_t gb = headoff + (size_t)qbase * HD;
        uint32_t st = sb + ASTG;
#pragma unroll
        for (int j = 0; j < 4; j++) {
            int c = tid + j * 256;
            int r = c >> 3;
            uint32_t dso = (uint32_t)r * AROW + (c & 7) * 16;
            size_t gso = gb + (size_t)r * HD + (c & 7) * 8;
            size_t kso = headoff + (size_t)r * HD + (c & 7) * 8;
            CP_ASYNC16(sb + AQ_H + dso, Qh + gso);
            CP_ASYNC16(sb + AQ_L + dso, Ql + gso);
            CP_ASYNC16(st + 0 * ATILE + dso, Kh + kso);
            CP_ASYNC16(st + 1 * ATILE + dso, Kl + kso);
            CP_ASYNC16(st + 2 * ATILE + dso, Vh + kso);
            CP_ASYNC16(st + 3 * ATILE + dso, Vl + kso);
        }
        CP_COMMIT();
    }

    // fragment lane addressing
    const uint32_t aq_lane = (uint32_t)(w * 16 + (l & 15)) * AROW + (l >> 4) * 16;
    const uint32_t kb_lane = (uint32_t)((l & 7) + ((l >> 4) * 8)) * AROW + ((l >> 3) & 1) * 16;
    const uint32_t v_lane  = (uint32_t)((l & 7) + ((l >> 3) & 1) * 8) * AROW + ((l >> 4) & 1) * 16;

    float oacc[8][4];
#pragma unroll
    for (int i = 0; i < 8; i++)
#pragma unroll
        for (int e = 0; e < 4; e++) oacc[i][e] = 0.0f;
    float rm0 = -INFINITY, rm1 = -INFINITY, rl0 = 0.0f, rl1 = 0.0f;

    const int row0 = qbase + w * 16 + (l >> 2);   // global q row for accum elems 0,1

    for (int kt = 0; kt <= qt; kt++) {
        if (kt < qt) { issue_kv(kt + 1); CP_WAIT1(); }
        else         { CP_WAIT0(); }
        __syncthreads();

        const uint32_t st = sb + ASTG + (uint32_t)(kt & 1) * ASTG_SZ;

        // ---- scores: S = Q @ K^T (3 passes) ----
        float sacc[16][4];
#pragma unroll
        for (int nt = 0; nt < 16; nt++)
#pragma unroll
            for (int e = 0; e < 4; e++) sacc[nt][e] = 0.0f;

#pragma unroll
        for (int ks = 0; ks < 4; ks++) {
            const uint32_t ko = ks * 32;
            uint32_t qhf[4], qlf[4];
            LDMX4(qhf[0], qhf[1], qhf[2], qhf[3], sb + AQ_H + aq_lane + ko);
            LDMX4(qlf[0], qlf[1], qlf[2], qlf[3], sb + AQ_L + aq_lane + ko);
#pragma unroll
            for (int nt2 = 0; nt2 < 8; nt2++) {
                uint32_t khf[4], klf[4];
                uint32_t kd = st + kb_lane + nt2 * (16 * AROW) + ko;
                LDMX4(khf[0], khf[1], khf[2], khf[3], kd);
                LDMX4(klf[0], klf[1], klf[2], klf[3], kd + ATILE);
                mma_bf16(sacc[2 * nt2],     qhf, &khf[0]);
                mma_bf16(sacc[2 * nt2 + 1], qhf, &khf[2]);
                mma_bf16(sacc[2 * nt2],     qhf, &klf[0]);
                mma_bf16(sacc[2 * nt2 + 1], qhf, &klf[2]);
                mma_bf16(sacc[2 * nt2],     qlf, &khf[0]);
                mma_bf16(sacc[2 * nt2 + 1], qlf, &khf[2]);
            }
        }

        // ---- causal mask (diagonal tile only) ----
        if (kt == qt) {
            const int cb = kt * 128 + (l & 3) * 2;
#pragma unroll
            for (int nt = 0; nt < 16; nt++) {
                int c = cb + nt * 8;
                if (c     > row0)     sacc[nt][0] = -NEG_VAL;
                if (c + 1 > row0)     sacc[nt][1] = -NEG_VAL;
                if (c     > row0 + 8) sacc[nt][2] = -NEG_VAL;
                if (c + 1 > row0 + 8) sacc[nt][3] = -NEG_VAL;
            }
        }

        // ---- online softmax (warp-local; rows live in quads) ----
        float mx0 = -INFINITY, mx1 = -INFINITY;
#pragma unroll
        for (int nt = 0; nt < 16; nt++) {
            mx0 = fmaxf(mx0, fmaxf(sacc[nt][0], sacc[nt][1]));
            mx1 = fmaxf(mx1, fmaxf(sacc[nt][2], sacc[nt][3]));
        }
        mx0 = fmaxf(mx0, __shfl_xor_sync(0xffffffffu, mx0, 1));
        mx0 = fmaxf(mx0, __shfl_xor_sync(0xffffffffu, mx0, 2));
        mx1 = fmaxf(mx1, __shfl_xor_sync(0xffffffffu, mx1, 1));
        mx1 = fmaxf(mx1, __shfl_xor_sync(0xffffffffu, mx1, 2));
        const float mn0 = fmaxf(rm0, mx0), mn1 = fmaxf(rm1, mx1);
        const float f0 = __expf(rm0 - mn0), f1 = __expf(rm1 - mn1);

        float s0 = 0.0f, s1 = 0.0f;
#pragma unroll
        for (int nt = 0; nt < 16; nt++) {
            float p0 = __expf(sacc[nt][0] - mn0);
            float p1 = __expf(sacc[nt][1] - mn0);
            float p2 = __expf(sacc[nt][2] - mn1);
            float p3 = __expf(sacc[nt][3] - mn1);
            sacc[nt][0] = p0; sacc[nt][1] = p1; sacc[nt][2] = p2; sacc[nt][3] = p3;
            s0 += p0 + p1; s1 += p2 + p3;
        }
        s0 += __shfl_xor_sync(0xffffffffu, s0, 1);
        s0 += __shfl_xor_sync(0xffffffffu, s0, 2);
        s1 += __shfl_xor_sync(0xffffffffu, s1, 1);
        s1 += __shfl_xor_sync(0xffffffffu, s1, 2);
        rl0 = rl0 * f0 + s0; rl1 = rl1 * f1 + s1;
        rm0 = mn0; rm1 = mn1;

#pragma unroll
        for (int i = 0; i < 8; i++) {
            oacc[i][0] *= f0; oacc[i][1] *= f0;
            oacc[i][2] *= f1; oacc[i][3] *= f1;
        }

        // ---- O += P @ V (3 passes, P converted in-register) ----
#pragma unroll
        for (int ks2 = 0; ks2 < 8; ks2++) {
            uint32_t aph[4], apl[4];
            float* p0 = sacc[2 * ks2];
            float* p1 = sacc[2 * ks2 + 1];
            aph[0] = pack_hi(p0[0], p0[1]);  apl[0] = pack_lo(p0[0], p0[1]);
            aph[1] = pack_hi(p0[2], p0[3]);  apl[1] = pack_lo(p0[2], p0[3]);
            aph[2] = pack_hi(p1[0], p1[1]);  apl[2] = pack_lo(p1[0], p1[1]);
            aph[3] = pack_hi(p1[2], p1[3]);  apl[3] = pack_lo(p1[2], p1[3]);

            const uint32_t kro = ks2 * (16 * AROW);
#pragma unroll
            for (int dv = 0; dv < 4; dv++) {
                uint32_t vhf[4], vlf[4];
                uint32_t va = st + 2 * ATILE + v_lane + kro + dv * 32;
                LDMX4T(vhf[0], vhf[1], vhf[2], vhf[3], va);
                LDMX4T(vlf[0], vlf[1], vlf[2], vlf[3], va + ATILE);
                mma_bf16(oacc[dv * 2],     aph, &vhf[0]);
                mma_bf16(oacc[dv * 2 + 1], aph, &vhf[2]);
                mma_bf16(oacc[dv * 2],     aph, &vlf[0]);
                mma_bf16(oacc[dv * 2 + 1], aph, &vlf[2]);
                mma_bf16(oacc[dv * 2],     apl, &vhf[0]);
                mma_bf16(oacc[dv * 2 + 1], apl, &vhf[2]);
            }
        }
        __syncthreads();
    }

    // ---- normalize, split, store merged-head layout ----
    const float i0 = 1.0f / rl0, i1 = 1.0f / rl1;
    const size_t grow0 = (size_t)(b * S_LEN + row0) * EMB;
#pragma unroll
    for (int nt8 = 0; nt8 < 8; nt8++) {
        int col = h * HD + nt8 * 8 + (l & 3) * 2;
        float v0 = oacc[nt8][0] * i0, v1 = oacc[nt8][1] * i0;
        float v2 = oacc[nt8][2] * i1, v3 = oacc[nt8][3] * i1;
        *(uint32_t*)(Ohi + grow0 + col)            = pack_hi(v0, v1);
        *(uint32_t*)(Olo + grow0 + col)            = pack_lo(v0, v1);
        *(uint32_t*)(Ohi + grow0 + 8 * EMB + col)  = pack_hi(v2, v3);
        *(uint32_t*)(Olo + grow0 + 8 * EMB + col)  = pack_lo(v2, v3);
    }
}

// ---------------------------------------------------------------------------
// Launch
// ---------------------------------------------------------------------------
extern "C" void kernel_launch(void* const* d_in, const int* in_sizes, int n_in,
                              void* d_out, int out_size)
{
    const float* x      = (const float*)d_in[0];
    const float* w_attn = (const float*)d_in[1];
    const float* b_attn = (const float*)d_in[2];
    const float* w_proj = (const float*)d_in[3];
    const float* b_proj = (const float*)d_in[4];
    float* out = (float*)d_out;

    float *qkv;
    ush *xhi, *xlo, *wah, *wal, *wph, *wpl, *athi, *atlo;
    ush *qh, *ql, *kh, *kl, *vh, *vl;
    cudaGetSymbolAddress((void**)&qkv,  g_qkv);
    cudaGetSymbolAddress((void**)&xhi,  g_xhi);
    cudaGetSymbolAddress((void**)&xlo,  g_xlo);
    cudaGetSymbolAddress((void**)&wah,  g_wah);
    cudaGetSymbolAddress((void**)&wal,  g_wal);
    cudaGetSymbolAddress((void**)&wph,  g_wph);
    cudaGetSymbolAddress((void**)&wpl,  g_wpl);
    cudaGetSymbolAddress((void**)&athi, g_athi);
    cudaGetSymbolAddress((void**)&atlo, g_atlo);
    cudaGetSymbolAddress((void**)&qh,   g_qh);
    cudaGetSymbolAddress((void**)&ql,   g_ql);
    cudaGetSymbolAddress((void**)&kh,   g_kh);
    cudaGetSymbolAddress((void**)&kl,   g_kl);
    cudaGetSymbolAddress((void**)&vh,   g_vh);
    cudaGetSymbolAddress((void**)&vl,   g_vl);

    cudaFuncSetAttribute(gemm_mma_split,
                         cudaFuncAttributeMaxDynamicSharedMemorySize, GEMM_SMEM);
    cudaFuncSetAttribute(attn_mma,
                         cudaFuncAttributeMaxDynamicSharedMemorySize, ATT_SMEM);

    // 1) split inputs/weights for QKV GEMM
    {
        int n = MTOT * EMB;
        convert_split<<<(n + 255) / 256, 256>>>(x, xhi, xlo, n);
        convert_transpose<<<dim3((3 * EMB) / 32, EMB / 32), dim3(32, 8)>>>(w_attn, wah, wal, EMB, 3 * EMB);
        convert_transpose<<<dim3(EMB / 32, EMB / 32), dim3(32, 8)>>>(w_proj, wph, wpl, EMB, EMB);
    }

    // 2) QKV projection
    {
        dim3 grid((3 * EMB) / 128, MTOT / 128);
        gemm_mma_split<<<grid, 256, GEMM_SMEM>>>(xhi, xlo, wah, wal, b_attn, qkv,
                                                 MTOT, 3 * EMB, EMB);
    }

    // 3) split qkv into per-head bf16 hi/lo (Q pre-scaled by 1/8)
    split_qkv<<<(MTOT * EMB / 2) / 256, 256>>>(qkv);

    // 4) attention (tensor-core flash)
    {
        dim3 grid(S_LEN / 128, HEADS, BATCH);
        attn_mma<<<grid, 256, ATT_SMEM>>>(qh, ql, kh, kl, vh, vl, athi, atlo);
    }

    // 5) output projection
    {
        dim3 grid(EMB / 128, MTOT / 128);
        gemm_mma_split<<<grid, 256, GEMM_SMEM>>>(athi, atlo, wph, wpl, b_proj, out,
                                                 MTOT, EMB, EMB);
    }
}

// round 7
// speedup vs baseline: 3.0548x; 1.1008x over previous
#include <cuda_runtime.h>
#include <cuda_bf16.h>
#include <math.h>
#include <stdint.h>

#define BATCH   2
#define S_LEN   2048
#define EMB     1024
#define HEADS   16
#define HD      64
#define NEG_VAL 100000.0f
#define MTOT    (BATCH * S_LEN)      // 4096

typedef unsigned short ush;

// ---------------------------------------------------------------------------
// Scratch (device globals; no runtime allocation allowed).
// ---------------------------------------------------------------------------
__device__ __align__(256) float g_qkv[(size_t)MTOT * 3 * EMB];   // [M, 3E] fp32
__device__ __align__(256) ush g_xhi[(size_t)MTOT * EMB];
__device__ __align__(256) ush g_xlo[(size_t)MTOT * EMB];
__device__ __align__(256) ush g_wah[(size_t)(3 * EMB) * EMB];
__device__ __align__(256) ush g_wal[(size_t)(3 * EMB) * EMB];
__device__ __align__(256) ush g_wph[(size_t)EMB * EMB];
__device__ __align__(256) ush g_wpl[(size_t)EMB * EMB];
__device__ __align__(256) ush g_athi[(size_t)MTOT * EMB];
__device__ __align__(256) ush g_atlo[(size_t)MTOT * EMB];
// Per-head split Q/K/V: [b][h][s][d]
__device__ __align__(256) ush g_qh[(size_t)MTOT * EMB];
__device__ __align__(256) ush g_ql[(size_t)MTOT * EMB];
__device__ __align__(256) ush g_kh[(size_t)MTOT * EMB];
__device__ __align__(256) ush g_kl[(size_t)MTOT * EMB];
__device__ __align__(256) ush g_vh[(size_t)MTOT * EMB];
__device__ __align__(256) ush g_vl[(size_t)MTOT * EMB];

// ---------------------------------------------------------------------------
// Helpers
// ---------------------------------------------------------------------------
__device__ __forceinline__ uint32_t smem_to_u32(const void* p) {
    uint32_t a;
    asm("{ .reg .u64 t; cvta.to.shared.u64 t, %1; cvt.u32.u64 %0, t; }" : "=r"(a) : "l"(p));
    return a;
}

#define CP_ASYNC16(dst, src) \
    asm volatile("cp.async.cg.shared.global [%0], [%1], 16;" :: "r"(dst), "l"(src))
#define CP_COMMIT() asm volatile("cp.async.commit_group;")
#define CP_WAIT1()  asm volatile("cp.async.wait_group 1;")
#define CP_WAIT0()  asm volatile("cp.async.wait_group 0;")

#define LDMX4(r0, r1, r2, r3, addr) \
    asm volatile("ldmatrix.sync.aligned.m8n8.x4.shared.b16 {%0,%1,%2,%3}, [%4];" \
                 : "=r"(r0), "=r"(r1), "=r"(r2), "=r"(r3) : "r"(addr))
#define LDMX4T(r0, r1, r2, r3, addr) \
    asm volatile("ldmatrix.sync.aligned.m8n8.x4.trans.shared.b16 {%0,%1,%2,%3}, [%4];" \
                 : "=r"(r0), "=r"(r1), "=r"(r2), "=r"(r3) : "r"(addr))

__device__ __forceinline__ void mma_bf16(float* d, const uint32_t* a, const uint32_t* b)
{
    asm volatile(
        "mma.sync.aligned.m16n8k16.row.col.f32.bf16.bf16.f32 "
        "{%0,%1,%2,%3}, {%4,%5,%6,%7}, {%8,%9}, {%0,%1,%2,%3};"
        : "+f"(d[0]), "+f"(d[1]), "+f"(d[2]), "+f"(d[3])
        : "r"(a[0]), "r"(a[1]), "r"(a[2]), "r"(a[3]), "r"(b[0]), "r"(b[1]));
}

// hi split via mantissa truncation (exact residual), pack two hi-bf16
__device__ __forceinline__ uint32_t pack_hi(float e, float o) {
    uint32_t r;
    asm("prmt.b32 %0, %1, %2, 0x7632;" : "=r"(r)
        : "r"(__float_as_uint(e)), "r"(__float_as_uint(o)));
    return r;
}
__device__ __forceinline__ uint32_t pack_lo(float e, float o) {
    float le = e - __uint_as_float(__float_as_uint(e) & 0xFFFF0000u);
    float lo = o - __uint_as_float(__float_as_uint(o) & 0xFFFF0000u);
    uint32_t r;
    asm("cvt.rn.bf16x2.f32 %0, %1, %2;" : "=r"(r) : "f"(lo), "f"(le));
    return r;
}

// ---------------------------------------------------------------------------
// fp32 -> bf16 hi/lo split (GEMM operand prep)
// ---------------------------------------------------------------------------
__global__ void convert_split(const float* __restrict__ in,
                              ush* __restrict__ hi, ush* __restrict__ lo, int n)
{
    int i = blockIdx.x * blockDim.x + threadIdx.x;
    if (i < n) {
        float v = in[i];
        __nv_bfloat16 h = __float2bfloat16(v);
        __nv_bfloat16 l = __float2bfloat16(v - __bfloat162float(h));
        hi[i] = *(ush*)&h;
        lo[i] = *(ush*)&l;
    }
}

__global__ void convert_transpose(const float* __restrict__ W,
                                  ush* __restrict__ hi, ush* __restrict__ lo,
                                  int K, int N)
{
    __shared__ float t[32][33];
    int n0 = blockIdx.x * 32, k0 = blockIdx.y * 32;
    int tx = threadIdx.x, ty = threadIdx.y;
#pragma unroll
    for (int i = 0; i < 4; i++)
        t[ty + i * 8][tx] = W[(size_t)(k0 + ty + i * 8) * N + n0 + tx];
    __syncthreads();
#pragma unroll
    for (int i = 0; i < 4; i++) {
        float v = t[tx][ty + i * 8];
        __nv_bfloat16 h = __float2bfloat16(v);
        __nv_bfloat16 l = __float2bfloat16(v - __bfloat162float(h));
        size_t o = (size_t)(n0 + ty + i * 8) * K + k0 + tx;
        hi[o] = *(ush*)&h;
        lo[o] = *(ush*)&l;
    }
}

// qkv fp32 [b,s,3E] -> per-head split bf16 [b,h,s,d]; Q pre-scaled by 1/8 (exact)
__global__ void split_qkv(const float* __restrict__ qkv)
{
    int j = blockIdx.x * 256 + threadIdx.x;            // pair index, 2^21 total
    int dp = j & 31;
    int s  = (j >> 5) & 2047;
    int h  = (j >> 16) & 15;
    int b  = j >> 20;
    size_t src = ((size_t)(b * S_LEN + s)) * (3 * EMB) + h * 192 + dp * 2;
    size_t dst = (((size_t)(b * HEADS + h) * S_LEN + s) * HD >> 1) + dp; // u32 index

    float2 q = *(const float2*)(qkv + src);
    float2 k = *(const float2*)(qkv + src + 64);
    float2 v = *(const float2*)(qkv + src + 128);
    q.x *= 0.125f; q.y *= 0.125f;

    ((uint32_t*)g_qh)[dst] = pack_hi(q.x, q.y);
    ((uint32_t*)g_ql)[dst] = pack_lo(q.x, q.y);
    ((uint32_t*)g_kh)[dst] = pack_hi(k.x, k.y);
    ((uint32_t*)g_kl)[dst] = pack_lo(k.x, k.y);
    ((uint32_t*)g_vh)[dst] = pack_hi(v.x, v.y);
    ((uint32_t*)g_vl)[dst] = pack_lo(v.x, v.y);
}

// ---------------------------------------------------------------------------
// mma.sync split-bf16 GEMM (validated R3). __launch_bounds__(256, 2) caps the
// allocator at 128 regs -> 2 CTAs/SM (regfile was the occupancy limiter at 130).
// ---------------------------------------------------------------------------
#define TROW      80
#define TILE_B    (128 * TROW)
#define STAGE_B   (4 * TILE_B)
#define GEMM_SMEM (2 * STAGE_B)          // 81920 -> 2 CTAs fit in 227KB

__global__ __launch_bounds__(256, 2) void gemm_mma_split(
    const ush* __restrict__ Ahi, const ush* __restrict__ Alo,
    const ush* __restrict__ Bhi, const ush* __restrict__ Blo,
    const float* __restrict__ bias, float* __restrict__ C,
    int M, int N, int K)
{
    extern __shared__ char smem[];
    const uint32_t sb0 = smem_to_u32(smem);
    const int tid = threadIdx.x;
    const int wid = tid >> 5;
    const int l   = tid & 31;
    const int bx = blockIdx.x;
    const int by = blockIdx.y;
    const int wm = wid >> 2;
    const int wn = wid & 3;

    int r0 = tid >> 2,         cc0 = tid & 3;
    int r1 = (tid + 256) >> 2, cc1 = tid & 3;
    uint32_t so0 = (uint32_t)r0 * TROW + cc0 * 16;
    uint32_t so1 = (uint32_t)r1 * TROW + cc1 * 16;
    size_t ga0 = (size_t)(by * 128 + r0) * K + cc0 * 8;
    size_t ga1 = (size_t)(by * 128 + r1) * K + cc1 * 8;
    size_t gb0 = (size_t)(bx * 128 + r0) * K + cc0 * 8;
    size_t gb1 = (size_t)(bx * 128 + r1) * K + cc1 * 8;

    const int NT = K / 32;

    auto issue = [&](int kt) {
        uint32_t sb = sb0 + (uint32_t)(kt & 1) * STAGE_B;
        size_t ko = (size_t)kt * 32;
        CP_ASYNC16(sb + 0 * TILE_B + so0, Ahi + ga0 + ko);
        CP_ASYNC16(sb + 0 * TILE_B + so1, Ahi + ga1 + ko);
        CP_ASYNC16(sb + 1 * TILE_B + so0, Alo + ga0 + ko);
        CP_ASYNC16(sb + 1 * TILE_B + so1, Alo + ga1 + ko);
        CP_ASYNC16(sb + 2 * TILE_B + so0, Bhi + gb0 + ko);
        CP_ASYNC16(sb + 2 * TILE_B + so1, Bhi + gb1 + ko);
        CP_ASYNC16(sb + 3 * TILE_B + so0, Blo + gb0 + ko);
        CP_ASYNC16(sb + 3 * TILE_B + so1, Blo + gb1 + ko);
        CP_COMMIT();
    };

    float acc[4][4][4];
#pragma unroll
    for (int mi = 0; mi < 4; mi++)
#pragma unroll
        for (int j = 0; j < 4; j++)
#pragma unroll
            for (int e = 0; e < 4; e++) acc[mi][j][e] = 0.0f;

    const uint32_t a_lane = (uint32_t)(wm * 64 + (l & 15)) * TROW + (l >> 4) * 16;
    const uint32_t b_lane = (uint32_t)(wn * 32 + (l & 7) + ((l >> 4) * 8)) * TROW
                          + ((l >> 3) & 1) * 16;

    issue(0);

    for (int kt = 0; kt < NT; kt++) {
        if (kt + 1 < NT) { issue(kt + 1); CP_WAIT1(); }
        else             { CP_WAIT0(); }
        __syncthreads();

        uint32_t sb = sb0 + (uint32_t)(kt & 1) * STAGE_B;

#pragma unroll
        for (int ks8 = 0; ks8 < 2; ks8++) {
            const uint32_t ko = ks8 * 32;
            uint32_t ah[4][4], al[4][4], bh[2][4], bl[2][4];
#pragma unroll
            for (int mi = 0; mi < 4; mi++) {
                uint32_t ad = sb + a_lane + mi * (16 * TROW) + ko;
                LDMX4(ah[mi][0], ah[mi][1], ah[mi][2], ah[mi][3], ad);
                LDMX4(al[mi][0], al[mi][1], al[mi][2], al[mi][3], ad + TILE_B);
            }
#pragma unroll
            for (int nb = 0; nb < 2; nb++) {
                uint32_t bd = sb + 2 * TILE_B + b_lane + nb * (16 * TROW) + ko;
                LDMX4(bh[nb][0], bh[nb][1], bh[nb][2], bh[nb][3], bd);
                LDMX4(bl[nb][0], bl[nb][1], bl[nb][2], bl[nb][3], bd + TILE_B);
            }
#pragma unroll
            for (int mi = 0; mi < 4; mi++)
#pragma unroll
                for (int j = 0; j < 4; j++)
                    mma_bf16(acc[mi][j], ah[mi], &bh[j >> 1][(j & 1) * 2]);
#pragma unroll
            for (int mi = 0; mi < 4; mi++)
#pragma unroll
                for (int j = 0; j < 4; j++)
                    mma_bf16(acc[mi][j], ah[mi], &bl[j >> 1][(j & 1) * 2]);
#pragma unroll
            for (int mi = 0; mi < 4; mi++)
#pragma unroll
                for (int j = 0; j < 4; j++)
                    mma_bf16(acc[mi][j], al[mi], &bh[j >> 1][(j & 1) * 2]);
        }
        __syncthreads();
    }

#pragma unroll
    for (int mi = 0; mi < 4; mi++) {
        int row = by * 128 + wm * 64 + mi * 16 + (l >> 2);
#pragma unroll
        for (int j = 0; j < 4; j++) {
            int col = bx * 128 + wn * 32 + j * 8 + (l & 3) * 2;
            float b0 = bias[col], b1 = bias[col + 1];
            float2 v0 = make_float2(acc[mi][j][0] + b0, acc[mi][j][1] + b1);
            float2 v1 = make_float2(acc[mi][j][2] + b0, acc[mi][j][3] + b1);
            *(float2*)(C + (size_t)row * N + col)       = v0;
            *(float2*)(C + (size_t)(row + 8) * N + col) = v1;
        }
    }
}

// ---------------------------------------------------------------------------
// Flash attention, split-bf16 mma.sync (validated R6).
// ---------------------------------------------------------------------------
#define AROW    144
#define ATILE   (128 * AROW)             // 18432
#define AQ_H    0
#define AQ_L    ATILE
#define ASTG    (2 * ATILE)              // stage base
#define ASTG_SZ (4 * ATILE)              // Kh,Kl,Vh,Vl per stage
#define ATT_SMEM (2 * ATILE + 2 * ASTG_SZ)   // 184320

__global__ __launch_bounds__(256) void attn_mma(
    const ush* __restrict__ Qh, const ush* __restrict__ Ql,
    const ush* __restrict__ Kh, const ush* __restrict__ Kl,
    const ush* __restrict__ Vh, const ush* __restrict__ Vl,
    ush* __restrict__ Ohi, ush* __restrict__ Olo)
{
    extern __shared__ char smem[];
    const uint32_t sb = smem_to_u32(smem);
    const int tid = threadIdx.x;
    const int w = tid >> 5;
    const int l = tid & 31;
    const int qt = (int)gridDim.x - 1 - (int)blockIdx.x;    // big tiles first
    const int h = blockIdx.y;
    const int b = blockIdx.z;
    const int qbase = qt * 128;

    const size_t headoff = (size_t)(b * HEADS + h) * S_LEN * HD;

    // 128x64 bf16 tile = 1024 16B-chunks; 4 per thread (8 chunks per row)
    auto issue_kv = [&](int kt) {
        uint32_t st = sb + ASTG + (uint32_t)(kt & 1) * ASTG_SZ;
        size_t gb = headoff + (size_t)kt * 128 * HD;
#pragma unroll
        for (int j = 0; j < 4; j++) {
            int c = tid + j * 256;
            int r = c >> 3;
            uint32_t dso = (uint32_t)r * AROW + (c & 7) * 16;
            size_t gso = gb + (size_t)r * HD + (c & 7) * 8;
            CP_ASYNC16(st + 0 * ATILE + dso, Kh + gso);
            CP_ASYNC16(st + 1 * ATILE + dso, Kl + gso);
            CP_ASYNC16(st + 2 * ATILE + dso, Vh + gso);
            CP_ASYNC16(st + 3 * ATILE + dso, Vl + gso);
        }
        CP_COMMIT();
    };

    // prologue group 0: Q tiles + KV stage 0
    {
        size_t gb = headoff + (size_t)qbase * HD;
        uint32_t st = sb + ASTG;
#pragma unroll
        for (int j = 0; j < 4; j++) {
            int c = tid + j * 256;
            int r = c >> 3;
            uint32_t dso = (uint32_t)r * AROW + (c & 7) * 16;
            size_t gso = gb + (size_t)r * HD + (c & 7) * 8;
            size_t kso = headoff + (size_t)r * HD + (c & 7) * 8;
            CP_ASYNC16(sb + AQ_H + dso, Qh + gso);
            CP_ASYNC16(sb + AQ_L + dso, Ql + gso);
            CP_ASYNC16(st + 0 * ATILE + dso, Kh + kso);
            CP_ASYNC16(st + 1 * ATILE + dso, Kl + kso);
            CP_ASYNC16(st + 2 * ATILE + dso, Vh + kso);
            CP_ASYNC16(st + 3 * ATILE + dso, Vl + kso);
        }
        CP_COMMIT();
    }

    // fragment lane addressing
    const uint32_t aq_lane = (uint32_t)(w * 16 + (l & 15)) * AROW + (l >> 4) * 16;
    const uint32_t kb_lane = (uint32_t)((l & 7) + ((l >> 4) * 8)) * AROW + ((l >> 3) & 1) * 16;
    const uint32_t v_lane  = (uint32_t)((l & 7) + ((l >> 3) & 1) * 8) * AROW + ((l >> 4) & 1) * 16;

    float oacc[8][4];
#pragma unroll
    for (int i = 0; i < 8; i++)
#pragma unroll
        for (int e = 0; e < 4; e++) oacc[i][e] = 0.0f;
    float rm0 = -INFINITY, rm1 = -INFINITY, rl0 = 0.0f, rl1 = 0.0f;

    const int row0 = qbase + w * 16 + (l >> 2);   // global q row for accum elems 0,1

    for (int kt = 0; kt <= qt; kt++) {
        if (kt < qt) { issue_kv(kt + 1); CP_WAIT1(); }
        else         { CP_WAIT0(); }
        __syncthreads();

        const uint32_t st = sb + ASTG + (uint32_t)(kt & 1) * ASTG_SZ;

        // ---- scores: S = Q @ K^T (3 passes) ----
        float sacc[16][4];
#pragma unroll
        for (int nt = 0; nt < 16; nt++)
#pragma unroll
            for (int e = 0; e < 4; e++) sacc[nt][e] = 0.0f;

#pragma unroll
        for (int ks = 0; ks < 4; ks++) {
            const uint32_t ko = ks * 32;
            uint32_t qhf[4], qlf[4];
            LDMX4(qhf[0], qhf[1], qhf[2], qhf[3], sb + AQ_H + aq_lane + ko);
            LDMX4(qlf[0], qlf[1], qlf[2], qlf[3], sb + AQ_L + aq_lane + ko);
#pragma unroll
            for (int nt2 = 0; nt2 < 8; nt2++) {
                uint32_t khf[4], klf[4];
                uint32_t kd = st + kb_lane + nt2 * (16 * AROW) + ko;
                LDMX4(khf[0], khf[1], khf[2], khf[3], kd);
                LDMX4(klf[0], klf[1], klf[2], klf[3], kd + ATILE);
                mma_bf16(sacc[2 * nt2],     qhf, &khf[0]);
                mma_bf16(sacc[2 * nt2 + 1], qhf, &khf[2]);
                mma_bf16(sacc[2 * nt2],     qhf, &klf[0]);
                mma_bf16(sacc[2 * nt2 + 1], qhf, &klf[2]);
                mma_bf16(sacc[2 * nt2],     qlf, &khf[0]);
                mma_bf16(sacc[2 * nt2 + 1], qlf, &khf[2]);
            }
        }

        // ---- causal mask (diagonal tile only) ----
        if (kt == qt) {
            const int cb = kt * 128 + (l & 3) * 2;
#pragma unroll
            for (int nt = 0; nt < 16; nt++) {
                int c = cb + nt * 8;
                if (c     > row0)     sacc[nt][0] = -NEG_VAL;
                if (c + 1 > row0)     sacc[nt][1] = -NEG_VAL;
                if (c     > row0 + 8) sacc[nt][2] = -NEG_VAL;
                if (c + 1 > row0 + 8) sacc[nt][3] = -NEG_VAL;
            }
        }

        // ---- online softmax (warp-local; rows live in quads) ----
        float mx0 = -INFINITY, mx1 = -INFINITY;
#pragma unroll
        for (int nt = 0; nt < 16; nt++) {
            mx0 = fmaxf(mx0, fmaxf(sacc[nt][0], sacc[nt][1]));
            mx1 = fmaxf(mx1, fmaxf(sacc[nt][2], sacc[nt][3]));
        }
        mx0 = fmaxf(mx0, __shfl_xor_sync(0xffffffffu, mx0, 1));
        mx0 = fmaxf(mx0, __shfl_xor_sync(0xffffffffu, mx0, 2));
        mx1 = fmaxf(mx1, __shfl_xor_sync(0xffffffffu, mx1, 1));
        mx1 = fmaxf(mx1, __shfl_xor_sync(0xffffffffu, mx1, 2));
        const float mn0 = fmaxf(rm0, mx0), mn1 = fmaxf(rm1, mx1);
        const float f0 = __expf(rm0 - mn0), f1 = __expf(rm1 - mn1);

        float s0 = 0.0f, s1 = 0.0f;
#pragma unroll
        for (int nt = 0; nt < 16; nt++) {
            float p0 = __expf(sacc[nt][0] - mn0);
            float p1 = __expf(sacc[nt][1] - mn0);
            float p2 = __expf(sacc[nt][2] - mn1);
            float p3 = __expf(sacc[nt][3] - mn1);
            sacc[nt][0] = p0; sacc[nt][1] = p1; sacc[nt][2] = p2; sacc[nt][3] = p3;
            s0 += p0 + p1; s1 += p2 + p3;
        }
        s0 += __shfl_xor_sync(0xffffffffu, s0, 1);
        s0 += __shfl_xor_sync(0xffffffffu, s0, 2);
        s1 += __shfl_xor_sync(0xffffffffu, s1, 1);
        s1 += __shfl_xor_sync(0xffffffffu, s1, 2);
        rl0 = rl0 * f0 + s0; rl1 = rl1 * f1 + s1;
        rm0 = mn0; rm1 = mn1;

#pragma unroll
        for (int i = 0; i < 8; i++) {
            oacc[i][0] *= f0; oacc[i][1] *= f0;
            oacc[i][2] *= f1; oacc[i][3] *= f1;
        }

        // ---- O += P @ V (3 passes, P converted in-register) ----
#pragma unroll
        for (int ks2 = 0; ks2 < 8; ks2++) {
            uint32_t aph[4], apl[4];
            float* p0 = sacc[2 * ks2];
            float* p1 = sacc[2 * ks2 + 1];
            aph[0] = pack_hi(p0[0], p0[1]);  apl[0] = pack_lo(p0[0], p0[1]);
            aph[1] = pack_hi(p0[2], p0[3]);  apl[1] = pack_lo(p0[2], p0[3]);
            aph[2] = pack_hi(p1[0], p1[1]);  apl[2] = pack_lo(p1[0], p1[1]);
            aph[3] = pack_hi(p1[2], p1[3]);  apl[3] = pack_lo(p1[2], p1[3]);

            const uint32_t kro = ks2 * (16 * AROW);
#pragma unroll
            for (int dv = 0; dv < 4; dv++) {
                uint32_t vhf[4], vlf[4];
                uint32_t va = st + 2 * ATILE + v_lane + kro + dv * 32;
                LDMX4T(vhf[0], vhf[1], vhf[2], vhf[3], va);
                LDMX4T(vlf[0], vlf[1], vlf[2], vlf[3], va + ATILE);
                mma_bf16(oacc[dv * 2],     aph, &vhf[0]);
                mma_bf16(oacc[dv * 2 + 1], aph, &vhf[2]);
                mma_bf16(oacc[dv * 2],     aph, &vlf[0]);
                mma_bf16(oacc[dv * 2 + 1], aph, &vlf[2]);
                mma_bf16(oacc[dv * 2],     apl, &vhf[0]);
                mma_bf16(oacc[dv * 2 + 1], apl, &vhf[2]);
            }
        }
        __syncthreads();
    }

    // ---- normalize, split, store merged-head layout ----
    const float i0 = 1.0f / rl0, i1 = 1.0f / rl1;
    const size_t grow0 = (size_t)(b * S_LEN + row0) * EMB;
#pragma unroll
    for (int nt8 = 0; nt8 < 8; nt8++) {
        int col = h * HD + nt8 * 8 + (l & 3) * 2;
        float v0 = oacc[nt8][0] * i0, v1 = oacc[nt8][1] * i0;
        float v2 = oacc[nt8][2] * i1, v3 = oacc[nt8][3] * i1;
        *(uint32_t*)(Ohi + grow0 + col)            = pack_hi(v0, v1);
        *(uint32_t*)(Olo + grow0 + col)            = pack_lo(v0, v1);
        *(uint32_t*)(Ohi + grow0 + 8 * EMB + col)  = pack_hi(v2, v3);
        *(uint32_t*)(Olo + grow0 + 8 * EMB + col)  = pack_lo(v2, v3);
    }
}

// ---------------------------------------------------------------------------
// Launch
// ---------------------------------------------------------------------------
extern "C" void kernel_launch(void* const* d_in, const int* in_sizes, int n_in,
                              void* d_out, int out_size)
{
    const float* x      = (const float*)d_in[0];
    const float* w_attn = (const float*)d_in[1];
    const float* b_attn = (const float*)d_in[2];
    const float* w_proj = (const float*)d_in[3];
    const float* b_proj = (const float*)d_in[4];
    float* out = (float*)d_out;

    float *qkv;
    ush *xhi, *xlo, *wah, *wal, *wph, *wpl, *athi, *atlo;
    ush *qh, *ql, *kh, *kl, *vh, *vl;
    cudaGetSymbolAddress((void**)&qkv,  g_qkv);
    cudaGetSymbolAddress((void**)&xhi,  g_xhi);
    cudaGetSymbolAddress((void**)&xlo,  g_xlo);
    cudaGetSymbolAddress((void**)&wah,  g_wah);
    cudaGetSymbolAddress((void**)&wal,  g_wal);
    cudaGetSymbolAddress((void**)&wph,  g_wph);
    cudaGetSymbolAddress((void**)&wpl,  g_wpl);
    cudaGetSymbolAddress((void**)&athi, g_athi);
    cudaGetSymbolAddress((void**)&atlo, g_atlo);
    cudaGetSymbolAddress((void**)&qh,   g_qh);
    cudaGetSymbolAddress((void**)&ql,   g_ql);
    cudaGetSymbolAddress((void**)&kh,   g_kh);
    cudaGetSymbolAddress((void**)&kl,   g_kl);
    cudaGetSymbolAddress((void**)&vh,   g_vh);
    cudaGetSymbolAddress((void**)&vl,   g_vl);

    cudaFuncSetAttribute(gemm_mma_split,
                         cudaFuncAttributeMaxDynamicSharedMemorySize, GEMM_SMEM);
    cudaFuncSetAttribute(attn_mma,
                         cudaFuncAttributeMaxDynamicSharedMemorySize, ATT_SMEM);

    // 1) split inputs/weights for QKV GEMM
    {
        int n = MTOT * EMB;
        convert_split<<<(n + 255) / 256, 256>>>(x, xhi, xlo, n);
        convert_transpose<<<dim3((3 * EMB) / 32, EMB / 32), dim3(32, 8)>>>(w_attn, wah, wal, EMB, 3 * EMB);
        convert_transpose<<<dim3(EMB / 32, EMB / 32), dim3(32, 8)>>>(w_proj, wph, wpl, EMB, EMB);
    }

    // 2) QKV projection
    {
        dim3 grid((3 * EMB) / 128, MTOT / 128);
        gemm_mma_split<<<grid, 256, GEMM_SMEM>>>(xhi, xlo, wah, wal, b_attn, qkv,
                                                 MTOT, 3 * EMB, EMB);
    }

    // 3) split qkv into per-head bf16 hi/lo (Q pre-scaled by 1/8)
    split_qkv<<<(MTOT * EMB / 2) / 256, 256>>>(qkv);

    // 4) attention (tensor-core flash)
    {
        dim3 grid(S_LEN / 128, HEADS, BATCH);
        attn_mma<<<grid, 256, ATT_SMEM>>>(qh, ql, kh, kl, vh, vl, athi, atlo);
    }

    // 5) output projection
    {
        dim3 grid(EMB / 128, MTOT / 128);
        gemm_mma_split<<<grid, 256, GEMM_SMEM>>>(athi, atlo, wph, wpl, b_proj, out,
                                                 MTOT, EMB, EMB);
    }
}